// round 5
// baseline (speedup 1.0000x reference)
#include <cuda_runtime.h>
#include <cuda_bf16.h>

// Problem constants: imgs [8,3,1024,1024] fp32, z [N,2] fp32, out [8,2] fp32
#define NY  1024
#define NX  1024
#define NB  8                // batches (channel-folded)
#define GBLOCK 256           // gather block: 64 points x 4 lanes
#define GPTS   64            // points per block per step
#define GATHER_BLOCKS 888    // 148 SMs * 6 resident blocks

// Scratch: channel-folded, pixel-major images P[y][x][b] (32 MiB, L2-resident)
__device__ __align__(128) float g_P[(size_t)NY * NX * NB];
__device__ float g_partial[GATHER_BLOCKS * 16];

// ---------------------------------------------------------------------------
// Kernel 1: fold+transpose  imgs[b*3+c][y][x] --sum_c--> g_P[y][x][b]
// (Frozen from R3: 21.5us @ DRAM 65.7%, near its 128MB traffic floor.)
// ---------------------------------------------------------------------------
__global__ void __launch_bounds__(128) fold_kernel(const float* __restrict__ imgs) {
    __shared__ float sm[128 * 9];          // pad 8->9 for conflict-free access
    const int y   = blockIdx.x >> 3;
    const int x0  = (blockIdx.x & 7) << 7;
    const int tid = threadIdx.x;

    #pragma unroll
    for (int b = 0; b < NB; b++) {
        float s = 0.f;
        #pragma unroll
        for (int c = 0; c < 3; c++)
            s += imgs[((size_t)(b * 3 + c) * NY + y) * NX + x0 + tid];
        sm[tid * 9 + b] = s;
    }
    __syncthreads();

    float4* out4 = reinterpret_cast<float4*>(g_P + ((size_t)y * NX + x0) * NB);
    #pragma unroll
    for (int k = 0; k < 2; k++) {
        int j   = k * 128 + tid;
        int pix = j >> 1, h = (j & 1) * 4;
        float4 v;
        v.x = sm[pix * 9 + h    ];
        v.y = sm[pix * 9 + h + 1];
        v.z = sm[pix * 9 + h + 2];
        v.w = sm[pix * 9 + h + 3];
        out4[j] = v;
    }
}

// ---------------------------------------------------------------------------
// Per-point step: 4 lanes per point. Lane (col, half): col selects pixel
// column x / x+1, half selects batches 0-3 / 4-7. Each lane loads float4 taps
// r0 (row yg) and r1 (row yg+1) and accumulates its linear share:
//   col 0 (holds g00,g10):  acc0 += w1x*(g10-g00);  acc1 += wyv*g10 - w1y*g00
//   col 1 (holds g01,g11):  acc0 += wxv*(g01-g11);  acc1 += w1y*g01 - wyv*g11
// Folded:  A = col? -wxv : w1x;  acc0 += A*(r1-r0)
//          B = sgn*wyv; C = sgn*w1y; acc1 += B*r1 - C*r0   (sgn = col? -1:+1)
// ---------------------------------------------------------------------------
__device__ __forceinline__ void proc_point(
    const float2* __restrict__ z2, const float* __restrict__ P,
    int p, int col, int laneOff, float sgn,
    float4& acc0, float4& acc1)
{
    float2 zz = __ldg(&z2[p]);
    float x0y = zz.x * 1023.0f;
    float x0x = zz.y * 1023.0f;
    bool oob = (x0y < 0.f) | (x0y > 1023.f) | (x0x < 0.f) | (x0x > 1023.f);
    if (oob) { x0y = 0.f; x0x = 0.f; }
    float ygf = floorf(x0y), xgf = floorf(x0x);
    int   yg = min((int)ygf, NY - 2);   // memory-safety clamp (never binds for z in [0,1))
    int   xg = min((int)xgf, NX - 2);
    float fy = ygf - x0y,  fx = xgf - x0x;     // in (-1, 0]
    float valid = oob ? 0.f : 1.f;
    float w1x = (1.f + fx) * valid, wxv = fx * valid;
    float w1y = (1.f + fy) * valid, wyv = fy * valid;

    float A = col ? -wxv : w1x;
    float B = sgn * wyv;
    float C = sgn * w1y;

    int i0 = (yg * NX + xg) * NB + laneOff;    // 16B-aligned
    float4 r0 = __ldg(reinterpret_cast<const float4*>(P + i0));
    float4 r1 = __ldg(reinterpret_cast<const float4*>(P + i0 + NB * NX));

    acc0.x = fmaf(A, r1.x - r0.x, acc0.x);
    acc0.y = fmaf(A, r1.y - r0.y, acc0.y);
    acc0.z = fmaf(A, r1.z - r0.z, acc0.z);
    acc0.w = fmaf(A, r1.w - r0.w, acc0.w);
    acc1.x = fmaf(B, r1.x, fmaf(-C, r0.x, acc1.x));
    acc1.y = fmaf(B, r1.y, fmaf(-C, r0.y, acc1.y));
    acc1.z = fmaf(B, r1.z, fmaf(-C, r0.z, acc1.z));
    acc1.w = fmaf(B, r1.w, fmaf(-C, r0.w, acc1.w));
}

// ---------------------------------------------------------------------------
// Kernel 2: float4 gather. Warp = 8 points x 4 lanes; each point's row-taps
// (x, x+1 .. 8 batches) are one 64B-contiguous LDG.128 pair. 3 warp-LDGs per
// 8 points. Unroll x2 for MLP. Deterministic fixed-order reduction.
// ---------------------------------------------------------------------------
__global__ void __launch_bounds__(GBLOCK, 4) gather_kernel(const float* __restrict__ z, int n) {
    const int t       = threadIdx.x;
    const int q       = t & 3;                      // quad lane
    const int col     = q >> 1;                     // 0: x, 1: x+1
    const int half    = q & 1;                      // batches 0-3 / 4-7
    const int laneOff = col * NB + half * 4;
    const float sgn   = col ? -1.f : 1.f;
    const int pl      = t >> 2;                     // point slot 0..63
    const int base    = blockIdx.x * GPTS + pl;
    const int S       = gridDim.x * GPTS;

    const float2* __restrict__ z2 = reinterpret_cast<const float2*>(z);
    const float*  __restrict__ P  = g_P;

    float4 acc0 = {0.f, 0.f, 0.f, 0.f}, acc1 = {0.f, 0.f, 0.f, 0.f};
    int p = base;
    for (; p + S < n; p += 2 * S) {
        proc_point(z2, P, p,     col, laneOff, sgn, acc0, acc1);
        proc_point(z2, P, p + S, col, laneOff, sgn, acc0, acc1);
    }
    for (; p < n; p += S)
        proc_point(z2, P, p, col, laneOff, sgn, acc0, acc1);

    __shared__ float s0[GBLOCK * 4], s1[GBLOCK * 4];
    *reinterpret_cast<float4*>(s0 + t * 4) = acc0;
    *reinterpret_cast<float4*>(s1 + t * 4) = acc1;
    __syncthreads();

    // Per-block partial: out[b][o], b = half*4+e. Fixed-order -> deterministic.
    if (t < 16) {
        int b = t >> 1, o = t & 1;
        int hb = b >> 2, e = b & 3;
        const float* src = o ? s1 : s0;
        float sum = 0.f;
        #pragma unroll 4
        for (int pp = 0; pp < GPTS; pp++) {
            int t0 = pp * 4 + hb;                   // col 0 lane
            sum += src[t0 * 4 + e] + src[(t0 + 2) * 4 + e];
        }
        g_partial[blockIdx.x * 16 + t] = sum;
    }
}

// ---------------------------------------------------------------------------
// Kernel 3: deterministic final reduction of GATHER_BLOCKS x 16 partials.
// ---------------------------------------------------------------------------
__global__ void __launch_bounds__(256) reduce_kernel(float* __restrict__ out) {
    __shared__ float red[256];
    const int tid = threadIdx.x;
    const int j = tid & 15, g = tid >> 4;        // 16 outputs x 16 lanes each
    float sum = 0.f;
    for (int i = g; i < GATHER_BLOCKS; i += 16)
        sum += g_partial[i * 16 + j];
    red[tid] = sum;
    __syncthreads();
    if (tid < 16) {
        float s2 = 0.f;
        #pragma unroll
        for (int g2 = 0; g2 < 16; g2++)
            s2 += red[g2 * 16 + tid];
        out[tid] = s2;
    }
}

extern "C" void kernel_launch(void* const* d_in, const int* in_sizes, int n_in,
                              void* d_out, int out_size) {
    const float* imgs = (const float*)d_in[0];   // 8*3*1024*1024 fp32
    const float* z    = (const float*)d_in[1];   // N*2 fp32
    const int n_pts   = in_sizes[1] / 2;

    fold_kernel<<<NY * (NX / 128), 128>>>(imgs);
    gather_kernel<<<GATHER_BLOCKS, GBLOCK>>>(z, n_pts);
    reduce_kernel<<<1, 256>>>((float*)d_out);
}